// round 14
// baseline (speedup 1.0000x reference)
#include <cuda_runtime.h>

#define NN 100000
#define CC 128
#define EE 800000
#define VV 50000
#define SLOPE 0.2f
#define SCAN_BLOCKS 98   // ceil(100000/1024)

// ---------------- device scratch (static: allocation-free rule) ----------------
__device__ float g_h[NN * CC];     // post-GEMM features of current layer
__device__ float g_x[NN * CC];     // aggregated output -> next layer input
__device__ float g_as[NN];
__device__ float g_ad[NN];
__device__ int   g_deg[NN];
__device__ int   g_off[NN + 1];
__device__ int   g_cur[NN];
__device__ int   g_csr[EE];
__device__ int   g_bsum[SCAN_BLOCKS];
__device__ int   g_bpre[SCAN_BLOCKS];

__device__ __forceinline__ float lrelu(float x) { return x > 0.f ? x : SLOPE * x; }

// ---------------- GEMM: h[n][c] = sum_k x[n][k] * W[c][k] ----------------
// block: 256 threads, tile 64 nodes x 128 channels. W transposed into smem with
// stride 129 (conflict-free reads & writes); x tile reads are warp-broadcast.
__global__ void gemm_kernel(const float* __restrict__ x, const float* __restrict__ W,
                            float* __restrict__ h) {
    extern __shared__ float sm[];
    float* sw = sm;                 // [128][129]
    float* sx = sm + 128 * 129;     // [64][128]
    const int tid = threadIdx.x;
    const int mb  = blockIdx.x * 64;

    for (int idx = tid; idx < CC * CC; idx += 256) {
        int c = idx >> 7, k = idx & 127;
        sw[k * 129 + c] = W[idx];
    }
    for (int idx = tid; idx < 64 * 32; idx += 256) {
        int m = idx >> 5, k4 = idx & 31;
        int row = mb + m;
        float4 v = (row < NN) ? *reinterpret_cast<const float4*>(x + (size_t)row * CC + k4 * 4)
                              : make_float4(0.f, 0.f, 0.f, 0.f);
        *reinterpret_cast<float4*>(sx + m * CC + k4 * 4) = v;
    }
    __syncthreads();

    const int c  = tid & 127;
    const int mh = tid >> 7;
    float acc[32];
#pragma unroll
    for (int m = 0; m < 32; m++) acc[m] = 0.f;
    const float* sxb = sx + (mh * 32) * CC;

    for (int k = 0; k < CC; k += 4) {
        float w0 = sw[(k + 0) * 129 + c];
        float w1 = sw[(k + 1) * 129 + c];
        float w2 = sw[(k + 2) * 129 + c];
        float w3 = sw[(k + 3) * 129 + c];
#pragma unroll
        for (int m = 0; m < 32; m++) {
            float4 xv = *reinterpret_cast<const float4*>(sxb + m * CC + k);
            acc[m] = fmaf(xv.x, w0, fmaf(xv.y, w1, fmaf(xv.z, w2, fmaf(xv.w, w3, acc[m]))));
        }
    }
#pragma unroll
    for (int m = 0; m < 32; m++) {
        int row = mb + mh * 32 + m;
        if (row < NN) h[(size_t)row * CC + c] = acc[m];
    }
}

// ---------------- per-node attention scores ----------------
__global__ void scores_kernel(const float* __restrict__ h, const float* __restrict__ av,
                              const float* __restrict__ dv) {
    int g = blockIdx.x * blockDim.x + threadIdx.x;
    int w = g >> 5, lane = g & 31;
    if (w >= NN) return;
    float4 hv = *reinterpret_cast<const float4*>(h + (size_t)w * CC + lane * 4);
    float4 a  = *reinterpret_cast<const float4*>(av + lane * 4);
    float4 d  = *reinterpret_cast<const float4*>(dv + lane * 4);
    float s = hv.x * a.x + hv.y * a.y + hv.z * a.z + hv.w * a.w;
    float t = hv.x * d.x + hv.y * d.y + hv.z * d.z + hv.w * d.w;
#pragma unroll
    for (int o = 16; o; o >>= 1) {
        s += __shfl_xor_sync(0xffffffffu, s, o);
        t += __shfl_xor_sync(0xffffffffu, t, o);
    }
    if (lane == 0) { g_as[w] = s; g_ad[w] = t; }
}

// ---------------- CSR build (dst-sorted) ----------------
__global__ void zero_deg_kernel() {
    int i = blockIdx.x * blockDim.x + threadIdx.x;
    if (i < NN) g_deg[i] = 0;
}

__global__ void count_kernel(const int* __restrict__ ed) {
    int e = blockIdx.x * blockDim.x + threadIdx.x;
    if (e < EE) atomicAdd(&g_deg[ed[EE + e]], 1);
}

__global__ void scan_block_kernel() {
    int i = blockIdx.x * 1024 + threadIdx.x;
    int v = (i < NN) ? g_deg[i] : 0;
    int lane = threadIdx.x & 31, w = threadIdx.x >> 5;
    int incl = v;
#pragma unroll
    for (int o = 1; o < 32; o <<= 1) {
        int t = __shfl_up_sync(0xffffffffu, incl, o);
        if (lane >= o) incl += t;
    }
    __shared__ int wsum[32];
    if (lane == 31) wsum[w] = incl;
    __syncthreads();
    if (w == 0) {
        int xv = wsum[lane];
#pragma unroll
        for (int o = 1; o < 32; o <<= 1) {
            int t = __shfl_up_sync(0xffffffffu, xv, o);
            if (lane >= o) xv += t;
        }
        wsum[lane] = xv;
    }
    __syncthreads();
    int excl = incl - v + (w ? wsum[w - 1] : 0);
    if (i < NN) g_off[i] = excl;                       // block-local exclusive
    if (threadIdx.x == 1023) g_bsum[blockIdx.x] = excl + v;  // block total
}

__global__ void scan_mid_kernel() {
    if (blockIdx.x == 0 && threadIdx.x == 0) {
        int run = 0;
        for (int b = 0; b < SCAN_BLOCKS; b++) { g_bpre[b] = run; run += g_bsum[b]; }
        g_off[NN] = run;
    }
}

__global__ void scan_add_kernel() {
    int i = blockIdx.x * 1024 + threadIdx.x;
    if (i < NN) {
        int o = g_off[i] + g_bpre[blockIdx.x];
        g_off[i] = o;
        g_cur[i] = o;
    }
}

__global__ void fill_kernel(const int* __restrict__ ed) {
    int e = blockIdx.x * blockDim.x + threadIdx.x;
    if (e < EE) {
        int dst = ed[EE + e];
        int p = atomicAdd(&g_cur[dst], 1);
        g_csr[p] = ed[e];   // store src node id
    }
}

// ---------------- gather-side softmax aggregation: one warp per dst node ----------------
__global__ void aggregate_kernel(const float* __restrict__ h, const float* __restrict__ bias,
                                 float* __restrict__ out) {
    int g = blockIdx.x * blockDim.x + threadIdx.x;
    int i = g >> 5, lane = g & 31;
    if (i >= NN) return;

    const float adi = g_ad[i];
    const int beg = g_off[i], end = g_off[i + 1];
    const float eself = lrelu(g_as[i] + adi);

    // pass 1: max (self-loop included)
    float m = eself;
    for (int j = beg + lane; j < end; j += 32)
        m = fmaxf(m, lrelu(g_as[g_csr[j]] + adi));
#pragma unroll
    for (int o = 16; o; o >>= 1) m = fmaxf(m, __shfl_xor_sync(0xffffffffu, m, o));

    // pass 2: exp-sum
    float ssum = 0.f;
    for (int j = beg + lane; j < end; j += 32)
        ssum += __expf(lrelu(g_as[g_csr[j]] + adi) - m);
#pragma unroll
    for (int o = 16; o; o >>= 1) ssum += __shfl_xor_sync(0xffffffffu, ssum, o);
    const float exs = __expf(eself - m);
    const float inv = 1.f / (ssum + exs + 1e-16f);

    // pass 3: weighted accumulate, lanes over channels (4 each)
    const int cb = lane * 4;
    float4 b4 = *reinterpret_cast<const float4*>(bias + cb);
    float4 hv = *reinterpret_cast<const float4*>(h + (size_t)i * CC + cb);
    const float asf = exs * inv;
    float4 acc;
    acc.x = fmaf(asf, hv.x, b4.x);
    acc.y = fmaf(asf, hv.y, b4.y);
    acc.z = fmaf(asf, hv.z, b4.z);
    acc.w = fmaf(asf, hv.w, b4.w);

    for (int j = beg; j < end; j++) {
        int s = g_csr[j];                                   // uniform across warp
        float alpha = __expf(lrelu(g_as[s] + adi) - m) * inv;
        float4 hs = *reinterpret_cast<const float4*>(h + (size_t)s * CC + cb);
        acc.x = fmaf(alpha, hs.x, acc.x);
        acc.y = fmaf(alpha, hs.y, acc.y);
        acc.z = fmaf(alpha, hs.z, acc.z);
        acc.w = fmaf(alpha, hs.w, acc.w);
    }
    *reinterpret_cast<float4*>(out + (size_t)i * CC + cb) = acc;
}

// ---------------- final index gather ----------------
__global__ void gather_kernel(const int* __restrict__ idx, float* __restrict__ out) {
    int g = blockIdx.x * blockDim.x + threadIdx.x;
    int r = g >> 5, lane = g & 31;
    if (r >= VV) return;
    int s = idx[r];
    *reinterpret_cast<float4*>(out + (size_t)r * CC + lane * 4) =
        *reinterpret_cast<const float4*>(g_x + (size_t)s * CC + lane * 4);
}

// ---------------- launch ----------------
static void run_layer(const float* xin, const float* W, const float* av, const float* dv,
                      const float* b, const int* ed, float* ph, float* px) {
    const int SMEM = (128 * 129 + 64 * 128) * 4;
    gemm_kernel<<<(NN + 63) / 64, 256, SMEM>>>(xin, W, ph);
    scores_kernel<<<(NN * 32 + 255) / 256, 256>>>(ph, av, dv);
    zero_deg_kernel<<<(NN + 255) / 256, 256>>>();
    count_kernel<<<(EE + 255) / 256, 256>>>(ed);
    scan_block_kernel<<<SCAN_BLOCKS, 1024>>>();
    scan_mid_kernel<<<1, 32>>>();
    scan_add_kernel<<<SCAN_BLOCKS, 1024>>>();
    fill_kernel<<<(EE + 255) / 256, 256>>>(ed);
    aggregate_kernel<<<(NN * 32 + 255) / 256, 256>>>(ph, b, px);
}

extern "C" void kernel_launch(void* const* d_in, const int* in_sizes, int n_in,
                              void* d_out, int out_size) {
    const float* emb = (const float*)d_in[0];
    const float* W1  = (const float*)d_in[1];
    const float* as1 = (const float*)d_in[2];
    const float* ad1 = (const float*)d_in[3];
    const float* b1  = (const float*)d_in[4];
    const float* W2  = (const float*)d_in[5];
    const float* as2 = (const float*)d_in[6];
    const float* ad2 = (const float*)d_in[7];
    const float* b2  = (const float*)d_in[8];
    const int*   e1  = (const int*)d_in[9];
    const int*   e2  = (const int*)d_in[10];
    const int*   idx = (const int*)d_in[11];
    float* out = (float*)d_out;

    const int SMEM = (128 * 129 + 64 * 128) * 4;
    cudaFuncSetAttribute(gemm_kernel, cudaFuncAttributeMaxDynamicSharedMemorySize, SMEM);

    float *ph = nullptr, *px = nullptr;
    cudaGetSymbolAddress((void**)&ph, g_h);
    cudaGetSymbolAddress((void**)&px, g_x);

    // layer 1: x = embedding -> g_x
    run_layer(emb, W1, as1, ad1, b1, e1, ph, px);
    // layer 2: x = g_x -> g_x (GEMM reads g_x into g_h first; strictly ordered on stream)
    run_layer(px, W2, as2, ad2, b2, e2, ph, px);
    // output gather
    gather_kernel<<<(VV * 32 + 255) / 256, 256>>>(idx, out);
}

// round 15
// speedup vs baseline: 1.0008x; 1.0008x over previous
#include <cuda_runtime.h>

#define NN 100000
#define CC 128
#define EE 800000
#define VV 50000
#define SLOPE 0.2f
#define SCAN_BLOCKS 98   // ceil(100000/1024)

// ---------------- device scratch (static: allocation-free rule) ----------------
__device__ float g_h[NN * CC];     // post-GEMM features of current layer
__device__ float g_x[NN * CC];     // aggregated output -> next layer input
__device__ float g_as[NN];
__device__ float g_ad[NN];
__device__ int   g_deg[NN];
__device__ int   g_off[NN + 1];
__device__ int   g_cur[NN];
__device__ int   g_csr[EE];
__device__ int   g_bsum[SCAN_BLOCKS];
__device__ int   g_bpre[SCAN_BLOCKS];

__device__ __forceinline__ float lrelu(float x) { return x > 0.f ? x : SLOPE * x; }

// ---------------- GEMM: h[n][c] = sum_k x[n][k] * W[c][k] ----------------
// block: 256 threads, tile 64 nodes x 128 channels. W transposed into smem with
// stride 129 (conflict-free reads & writes); x tile reads are warp-broadcast.
__global__ void gemm_kernel(const float* __restrict__ x, const float* __restrict__ W,
                            float* __restrict__ h) {
    extern __shared__ float sm[];
    float* sw = sm;                 // [128][129]
    float* sx = sm + 128 * 129;     // [64][128]
    const int tid = threadIdx.x;
    const int mb  = blockIdx.x * 64;

    for (int idx = tid; idx < CC * CC; idx += 256) {
        int c = idx >> 7, k = idx & 127;
        sw[k * 129 + c] = W[idx];
    }
    for (int idx = tid; idx < 64 * 32; idx += 256) {
        int m = idx >> 5, k4 = idx & 31;
        int row = mb + m;
        float4 v = (row < NN) ? *reinterpret_cast<const float4*>(x + (size_t)row * CC + k4 * 4)
                              : make_float4(0.f, 0.f, 0.f, 0.f);
        *reinterpret_cast<float4*>(sx + m * CC + k4 * 4) = v;
    }
    __syncthreads();

    const int c  = tid & 127;
    const int mh = tid >> 7;
    float acc[32];
#pragma unroll
    for (int m = 0; m < 32; m++) acc[m] = 0.f;
    const float* sxb = sx + (mh * 32) * CC;

    for (int k = 0; k < CC; k += 4) {
        float w0 = sw[(k + 0) * 129 + c];
        float w1 = sw[(k + 1) * 129 + c];
        float w2 = sw[(k + 2) * 129 + c];
        float w3 = sw[(k + 3) * 129 + c];
#pragma unroll
        for (int m = 0; m < 32; m++) {
            float4 xv = *reinterpret_cast<const float4*>(sxb + m * CC + k);
            acc[m] = fmaf(xv.x, w0, fmaf(xv.y, w1, fmaf(xv.z, w2, fmaf(xv.w, w3, acc[m]))));
        }
    }
#pragma unroll
    for (int m = 0; m < 32; m++) {
        int row = mb + mh * 32 + m;
        if (row < NN) h[(size_t)row * CC + c] = acc[m];
    }
}

// ---------------- per-node attention scores ----------------
__global__ void scores_kernel(const float* __restrict__ h, const float* __restrict__ av,
                              const float* __restrict__ dv) {
    int g = blockIdx.x * blockDim.x + threadIdx.x;
    int w = g >> 5, lane = g & 31;
    if (w >= NN) return;
    float4 hv = *reinterpret_cast<const float4*>(h + (size_t)w * CC + lane * 4);
    float4 a  = *reinterpret_cast<const float4*>(av + lane * 4);
    float4 d  = *reinterpret_cast<const float4*>(dv + lane * 4);
    float s = hv.x * a.x + hv.y * a.y + hv.z * a.z + hv.w * a.w;
    float t = hv.x * d.x + hv.y * d.y + hv.z * d.z + hv.w * d.w;
#pragma unroll
    for (int o = 16; o; o >>= 1) {
        s += __shfl_xor_sync(0xffffffffu, s, o);
        t += __shfl_xor_sync(0xffffffffu, t, o);
    }
    if (lane == 0) { g_as[w] = s; g_ad[w] = t; }
}

// ---------------- CSR build (dst-sorted) ----------------
__global__ void zero_deg_kernel() {
    int i = blockIdx.x * blockDim.x + threadIdx.x;
    if (i < NN) g_deg[i] = 0;
}

__global__ void count_kernel(const int* __restrict__ ed) {
    int e = blockIdx.x * blockDim.x + threadIdx.x;
    if (e < EE) atomicAdd(&g_deg[ed[EE + e]], 1);
}

__global__ void scan_block_kernel() {
    int i = blockIdx.x * 1024 + threadIdx.x;
    int v = (i < NN) ? g_deg[i] : 0;
    int lane = threadIdx.x & 31, w = threadIdx.x >> 5;
    int incl = v;
#pragma unroll
    for (int o = 1; o < 32; o <<= 1) {
        int t = __shfl_up_sync(0xffffffffu, incl, o);
        if (lane >= o) incl += t;
    }
    __shared__ int wsum[32];
    if (lane == 31) wsum[w] = incl;
    __syncthreads();
    if (w == 0) {
        int xv = wsum[lane];
#pragma unroll
        for (int o = 1; o < 32; o <<= 1) {
            int t = __shfl_up_sync(0xffffffffu, xv, o);
            if (lane >= o) xv += t;
        }
        wsum[lane] = xv;
    }
    __syncthreads();
    int excl = incl - v + (w ? wsum[w - 1] : 0);
    if (i < NN) g_off[i] = excl;                       // block-local exclusive
    if (threadIdx.x == 1023) g_bsum[blockIdx.x] = excl + v;  // block total
}

__global__ void scan_mid_kernel() {
    if (blockIdx.x == 0 && threadIdx.x == 0) {
        int run = 0;
        for (int b = 0; b < SCAN_BLOCKS; b++) { g_bpre[b] = run; run += g_bsum[b]; }
        g_off[NN] = run;
    }
}

__global__ void scan_add_kernel() {
    int i = blockIdx.x * 1024 + threadIdx.x;
    if (i < NN) {
        int o = g_off[i] + g_bpre[blockIdx.x];
        g_off[i] = o;
        g_cur[i] = o;
    }
}

__global__ void fill_kernel(const int* __restrict__ ed) {
    int e = blockIdx.x * blockDim.x + threadIdx.x;
    if (e < EE) {
        int dst = ed[EE + e];
        int p = atomicAdd(&g_cur[dst], 1);
        g_csr[p] = ed[e];   // store src node id
    }
}

// ---------------- gather-side softmax aggregation: one warp per dst node ----------------
__global__ void aggregate_kernel(const float* __restrict__ h, const float* __restrict__ bias,
                                 float* __restrict__ out) {
    int g = blockIdx.x * blockDim.x + threadIdx.x;
    int i = g >> 5, lane = g & 31;
    if (i >= NN) return;

    const float adi = g_ad[i];
    const int beg = g_off[i], end = g_off[i + 1];
    const float eself = lrelu(g_as[i] + adi);

    // pass 1: max (self-loop included)
    float m = eself;
    for (int j = beg + lane; j < end; j += 32)
        m = fmaxf(m, lrelu(g_as[g_csr[j]] + adi));
#pragma unroll
    for (int o = 16; o; o >>= 1) m = fmaxf(m, __shfl_xor_sync(0xffffffffu, m, o));

    // pass 2: exp-sum
    float ssum = 0.f;
    for (int j = beg + lane; j < end; j += 32)
        ssum += __expf(lrelu(g_as[g_csr[j]] + adi) - m);
#pragma unroll
    for (int o = 16; o; o >>= 1) ssum += __shfl_xor_sync(0xffffffffu, ssum, o);
    const float exs = __expf(eself - m);
    const float inv = 1.f / (ssum + exs + 1e-16f);

    // pass 3: weighted accumulate, lanes over channels (4 each)
    const int cb = lane * 4;
    float4 b4 = *reinterpret_cast<const float4*>(bias + cb);
    float4 hv = *reinterpret_cast<const float4*>(h + (size_t)i * CC + cb);
    const float asf = exs * inv;
    float4 acc;
    acc.x = fmaf(asf, hv.x, b4.x);
    acc.y = fmaf(asf, hv.y, b4.y);
    acc.z = fmaf(asf, hv.z, b4.z);
    acc.w = fmaf(asf, hv.w, b4.w);

    for (int j = beg; j < end; j++) {
        int s = g_csr[j];                                   // uniform across warp
        float alpha = __expf(lrelu(g_as[s] + adi) - m) * inv;
        float4 hs = *reinterpret_cast<const float4*>(h + (size_t)s * CC + cb);
        acc.x = fmaf(alpha, hs.x, acc.x);
        acc.y = fmaf(alpha, hs.y, acc.y);
        acc.z = fmaf(alpha, hs.z, acc.z);
        acc.w = fmaf(alpha, hs.w, acc.w);
    }
    *reinterpret_cast<float4*>(out + (size_t)i * CC + cb) = acc;
}

// ---------------- final index gather ----------------
__global__ void gather_kernel(const int* __restrict__ idx, float* __restrict__ out) {
    int g = blockIdx.x * blockDim.x + threadIdx.x;
    int r = g >> 5, lane = g & 31;
    if (r >= VV) return;
    int s = idx[r];
    *reinterpret_cast<float4*>(out + (size_t)r * CC + lane * 4) =
        *reinterpret_cast<const float4*>(g_x + (size_t)s * CC + lane * 4);
}

// ---------------- launch ----------------
static void run_layer(const float* xin, const float* W, const float* av, const float* dv,
                      const float* b, const int* ed, float* ph, float* px) {
    const int SMEM = (128 * 129 + 64 * 128) * 4;
    gemm_kernel<<<(NN + 63) / 64, 256, SMEM>>>(xin, W, ph);
    scores_kernel<<<(NN * 32 + 255) / 256, 256>>>(ph, av, dv);
    zero_deg_kernel<<<(NN + 255) / 256, 256>>>();
    count_kernel<<<(EE + 255) / 256, 256>>>(ed);
    scan_block_kernel<<<SCAN_BLOCKS, 1024>>>();
    scan_mid_kernel<<<1, 32>>>();
    scan_add_kernel<<<SCAN_BLOCKS, 1024>>>();
    fill_kernel<<<(EE + 255) / 256, 256>>>(ed);
    aggregate_kernel<<<(NN * 32 + 255) / 256, 256>>>(ph, b, px);
}

extern "C" void kernel_launch(void* const* d_in, const int* in_sizes, int n_in,
                              void* d_out, int out_size) {
    const float* emb = (const float*)d_in[0];
    const float* W1  = (const float*)d_in[1];
    const float* as1 = (const float*)d_in[2];
    const float* ad1 = (const float*)d_in[3];
    const float* b1  = (const float*)d_in[4];
    const float* W2  = (const float*)d_in[5];
    const float* as2 = (const float*)d_in[6];
    const float* ad2 = (const float*)d_in[7];
    const float* b2  = (const float*)d_in[8];
    const int*   e1  = (const int*)d_in[9];
    const int*   e2  = (const int*)d_in[10];
    const int*   idx = (const int*)d_in[11];
    float* out = (float*)d_out;

    const int SMEM = (128 * 129 + 64 * 128) * 4;
    cudaFuncSetAttribute(gemm_kernel, cudaFuncAttributeMaxDynamicSharedMemorySize, SMEM);

    float *ph = nullptr, *px = nullptr;
    cudaGetSymbolAddress((void**)&ph, g_h);
    cudaGetSymbolAddress((void**)&px, g_x);

    // layer 1: x = embedding -> g_x
    run_layer(emb, W1, as1, ad1, b1, e1, ph, px);
    // layer 2: x = g_x -> g_x (GEMM reads g_x into g_h first; strictly ordered on stream)
    run_layer(px, W2, as2, ad2, b2, e2, ph, px);
    // output gather
    gather_kernel<<<(VV * 32 + 255) / 256, 256>>>(idx, out);
}